// round 2
// baseline (speedup 1.0000x reference)
#include <cuda_runtime.h>
#include <math.h>

#define NN 50000
#define NE 800000
#define INC 128
#define D 64

// ---------------- scratch (static device globals; no allocation) ------------
__device__ float g_vq[INC];          // weight_n @ (query @ att_w[:d])
__device__ float g_tk[D];            // key_w @ att_w[d:2d]
__device__ float g_ce;               // weight_e[0,:] . att_w[2d:]
__device__ float g_W1[INC * D];      // weight_n @ out_w[:d]
__device__ float g_hsrc[(size_t)NN * D];
__device__ float g_qa[NN];
__device__ float g_ka[NN];
__device__ float g_agg[(size_t)NN * D];
__device__ int   g_start[NN + 1];

// ---------------- packed f32x2 helpers (Blackwell FFMA2) --------------------
__device__ __forceinline__ unsigned long long pk2(float lo, float hi) {
    unsigned long long r;
    asm("mov.b64 %0, {%1, %2};" : "=l"(r) : "f"(lo), "f"(hi));
    return r;
}
__device__ __forceinline__ void fma2(unsigned long long& d,
                                     unsigned long long a, unsigned long long b) {
    asm("fma.rn.f32x2 %0, %1, %2, %0;" : "+l"(d) : "l"(a), "l"(b));
}
__device__ __forceinline__ float2 up2(unsigned long long v) {
    float lo, hi;
    asm("mov.b64 {%0, %1}, %2;" : "=f"(lo), "=f"(hi) : "l"(v));
    return make_float2(lo, hi);
}

// ---------------- K_pre: fold small matrices (1 block) ----------------------
__global__ void k_pre(const float* __restrict__ wn,
                      const float* __restrict__ we,
                      const float* __restrict__ query,
                      const float* __restrict__ key_w,
                      const float* __restrict__ att_w,
                      const float* __restrict__ out_w) {
    __shared__ float s_aw[3 * D];
    __shared__ float s_tq[D];
    __shared__ float s_ow[D * D];
    int t = threadIdx.x;             // 256 threads
    for (int i = t; i < 3 * D; i += 256) s_aw[i] = att_w[i];
    for (int i = t; i < D * D; i += 256) s_ow[i] = out_w[i];
    __syncthreads();
    if (t < D) {
        float sq = 0.f, sk = 0.f;
        for (int j = 0; j < D; j++) {
            sq += query[t * D + j] * s_aw[j];
            sk += key_w[t * D + j] * s_aw[D + j];
        }
        s_tq[t] = sq;
        g_tk[t] = sk;
    }
    if (t == 0) {
        float c = 0.f;
        for (int j = 0; j < D; j++) c += we[j] * s_aw[2 * D + j];
        g_ce = c;
    }
    __syncthreads();
    if (t < INC) {
        float vq = 0.f;
        for (int i = 0; i < D; i++) vq += wn[t * D + i] * s_tq[i];
        g_vq[t] = vq;
    }
    for (int idx = t; idx < INC * D; idx += 256) {
        int k = idx >> 6, c = idx & 63;
        float s = 0.f;
        #pragma unroll 8
        for (int j = 0; j < D; j++) s += wn[k * D + j] * s_ow[j * D + c];
        g_W1[idx] = s;
    }
}

// ---------------- K_mm1: h_src = feat_src @ W_n  (+ ka epilogue) ------------
// 128-row tile, 128 threads, 8x8 micro-tile, packed f32x2 FMAs
#define SA1 129
__global__ void k_mm1(const float* __restrict__ feat,
                      const float* __restrict__ wn, int n_rows) {
    extern __shared__ float sm[];
    float* As = sm;                  // 128 x SA1 (row-major, padded)
    float* Ws = sm + 128 * SA1;      // 128 x 64
    int row0 = blockIdx.x * 128;
    int t = threadIdx.x;
    float4* Ws4 = (float4*)Ws;
    const float4* wn4 = (const float4*)wn;
    for (int i = t; i < INC * D / 4; i += 128) Ws4[i] = wn4[i];
    int nr = n_rows - row0; if (nr > 128) nr = 128;
    const float4* f4 = (const float4*)(feat + (size_t)row0 * INC);
    for (int i = t; i < 128 * 32; i += 128) {
        int r = i >> 5, c4 = i & 31;
        float4 v = (r < nr) ? f4[i] : make_float4(0.f, 0.f, 0.f, 0.f);
        float* p = &As[r * SA1 + c4 * 4];
        p[0] = v.x; p[1] = v.y; p[2] = v.z; p[3] = v.w;
    }
    __syncthreads();
    int tx = t & 7, ty = t >> 3;
    int r0 = ty * 8, c0 = tx * 8;
    unsigned long long acc[8][4] = {};
    #pragma unroll 4
    for (int k = 0; k < INC; k++) {
        float4 b0 = *(const float4*)&Ws[k * D + c0];
        float4 b1 = *(const float4*)&Ws[k * D + c0 + 4];
        unsigned long long bb0 = pk2(b0.x, b0.y), bb1 = pk2(b0.z, b0.w);
        unsigned long long bb2 = pk2(b1.x, b1.y), bb3 = pk2(b1.z, b1.w);
        #pragma unroll
        for (int i = 0; i < 8; i++) {
            float a = As[(r0 + i) * SA1 + k];
            unsigned long long aa = pk2(a, a);
            fma2(acc[i][0], aa, bb0);
            fma2(acc[i][1], aa, bb1);
            fma2(acc[i][2], aa, bb2);
            fma2(acc[i][3], aa, bb3);
        }
    }
    float tkv[8];
    #pragma unroll
    for (int j = 0; j < 8; j++) tkv[j] = g_tk[c0 + j];
    #pragma unroll
    for (int i = 0; i < 8; i++) {
        int r = row0 + r0 + i;
        float2 p0 = up2(acc[i][0]), p1 = up2(acc[i][1]);
        float2 p2 = up2(acc[i][2]), p3 = up2(acc[i][3]);
        if (r < n_rows) {
            *(float4*)&g_hsrc[(size_t)r * D + c0]     = make_float4(p0.x, p0.y, p1.x, p1.y);
            *(float4*)&g_hsrc[(size_t)r * D + c0 + 4] = make_float4(p2.x, p2.y, p3.x, p3.y);
        }
        float ka = p0.x * tkv[0] + p0.y * tkv[1] + p1.x * tkv[2] + p1.y * tkv[3]
                 + p2.x * tkv[4] + p2.y * tkv[5] + p3.x * tkv[6] + p3.y * tkv[7];
        ka += __shfl_xor_sync(0xffffffffu, ka, 1);
        ka += __shfl_xor_sync(0xffffffffu, ka, 2);
        ka += __shfl_xor_sync(0xffffffffu, ka, 4);
        if (tx == 0 && r < n_rows) g_ka[r] = ka;
    }
}

// ---------------- K_qa: qa = feat_dst . vq  (warp per node) -----------------
__global__ void k_qa(const float* __restrict__ feat_dst, int n_nodes) {
    int w = (blockIdx.x * blockDim.x + threadIdx.x) >> 5;
    int lane = threadIdx.x & 31;
    if (w >= n_nodes) return;
    const float* fd = feat_dst + (size_t)w * INC;
    float qa = 0.f;
    #pragma unroll
    for (int j = 0; j < INC; j += 32) qa += fd[j + lane] * g_vq[j + lane];
    #pragma unroll
    for (int o = 16; o > 0; o >>= 1) qa += __shfl_xor_sync(0xffffffffu, qa, o);
    if (lane == 0) g_qa[w] = qa;
}

// ---------------- K_bounds: segment starts via scatter over edges -----------
__global__ void k_bounds(const int* __restrict__ dst, int n_nodes, int n_edges) {
    int e = blockIdx.x * blockDim.x + threadIdx.x;
    if (e > n_edges) return;
    int d1 = (e < n_edges) ? dst[e] : n_nodes;
    int d0 = (e > 0) ? dst[e - 1] : -1;
    for (int n = d0 + 1; n <= d1; n++) g_start[n] = e;
}

// ---------------- K_agg: fused logits + segment softmax + message sum -------
// half-warp (16 lanes x float4) per destination node, logits recomputed
__global__ void k_agg(const int* __restrict__ src_idx,
                      const float* __restrict__ ew,
                      const float* __restrict__ att_b, int n_nodes) {
    int hw = (blockIdx.x * blockDim.x + threadIdx.x) >> 4;
    int sl = threadIdx.x & 15;
    unsigned mask = 0xFFFFu << (threadIdx.x & 16);
    if (hw >= n_nodes) return;
    int e0 = g_start[hw], e1 = g_start[hw + 1];
    float4* aggp = (float4*)&g_agg[(size_t)hw * D];
    if (e0 == e1) { aggp[sl] = make_float4(0.f, 0.f, 0.f, 0.f); return; }
    float qn = g_qa[hw] + att_b[0];
    float ce = g_ce;
    float m = -INFINITY;
    for (int e = e0 + sl; e < e1; e += 16) {
        float x = qn + g_ka[src_idx[e]] + ew[e] * ce;
        x = (x >= 0.f) ? x : 0.2f * x;
        m = fmaxf(m, x);
    }
    #pragma unroll
    for (int o = 8; o > 0; o >>= 1) m = fmaxf(m, __shfl_xor_sync(mask, m, o));
    float s = 0.f;
    for (int e = e0 + sl; e < e1; e += 16) {
        float x = qn + g_ka[src_idx[e]] + ew[e] * ce;
        x = (x >= 0.f) ? x : 0.2f * x;
        s += __expf(x - m);
    }
    #pragma unroll
    for (int o = 8; o > 0; o >>= 1) s += __shfl_xor_sync(mask, s, o);
    float inv = 1.f / (s + 1e-16f);
    float4 acc = make_float4(0.f, 0.f, 0.f, 0.f);
    for (int e = e0; e < e1; e++) {
        int si = src_idx[e];                       // broadcast within half-warp
        float x = qn + g_ka[si] + ew[e] * ce;
        x = (x >= 0.f) ? x : 0.2f * x;
        float al = __expf(x - m) * inv;
        float4 h = *(const float4*)&g_hsrc[(size_t)si * D + 4 * sl];
        acc.x += al * h.x; acc.y += al * h.y; acc.z += al * h.z; acc.w += al * h.w;
    }
    aggp[sl] = acc;
}

// ---------------- K_mm2: out = feat_dst@W1 + agg@out_w[64:] + b (K=192) -----
#define SA2 193
__global__ void k_mm2(const float* __restrict__ feat_dst,
                      const float* __restrict__ out_w,
                      const float* __restrict__ out_b,
                      float* __restrict__ out, int n_rows) {
    extern __shared__ float sm[];
    const int KK = INC + D;          // 192
    float* As = sm;                  // 128 x SA2
    float* Ws = sm + 128 * SA2;      // 192 x 64
    int row0 = blockIdx.x * 128;
    int t = threadIdx.x;
    float4* Ws4 = (float4*)Ws;
    const float4* w14 = (const float4*)g_W1;
    for (int i = t; i < INC * D / 4; i += 128) Ws4[i] = w14[i];
    const float4* ow4 = (const float4*)(out_w + D * D);
    for (int i = t; i < D * D / 4; i += 128) Ws4[INC * D / 4 + i] = ow4[i];
    int nr = n_rows - row0; if (nr > 128) nr = 128;
    const float4* f4 = (const float4*)(feat_dst + (size_t)row0 * INC);
    for (int i = t; i < 128 * 32; i += 128) {
        int r = i >> 5, c4 = i & 31;
        float4 v = (r < nr) ? f4[i] : make_float4(0.f, 0.f, 0.f, 0.f);
        float* p = &As[r * SA2 + c4 * 4];
        p[0] = v.x; p[1] = v.y; p[2] = v.z; p[3] = v.w;
    }
    const float4* a4 = (const float4*)(g_agg + (size_t)row0 * D);
    for (int i = t; i < 128 * 16; i += 128) {
        int r = i >> 4, c4 = i & 15;
        float4 v = (r < nr) ? a4[i] : make_float4(0.f, 0.f, 0.f, 0.f);
        float* p = &As[r * SA2 + INC + c4 * 4];
        p[0] = v.x; p[1] = v.y; p[2] = v.z; p[3] = v.w;
    }
    __syncthreads();
    int tx = t & 7, ty = t >> 3;
    int r0 = ty * 8, c0 = tx * 8;
    float4 ob0 = *(const float4*)&out_b[c0];
    float4 ob1 = *(const float4*)&out_b[c0 + 4];
    unsigned long long bias[4] = { pk2(ob0.x, ob0.y), pk2(ob0.z, ob0.w),
                                   pk2(ob1.x, ob1.y), pk2(ob1.z, ob1.w) };
    unsigned long long acc[8][4];
    #pragma unroll
    for (int i = 0; i < 8; i++)
        #pragma unroll
        for (int j = 0; j < 4; j++) acc[i][j] = bias[j];
    #pragma unroll 4
    for (int k = 0; k < KK; k++) {
        float4 b0 = *(const float4*)&Ws[k * D + c0];
        float4 b1 = *(const float4*)&Ws[k * D + c0 + 4];
        unsigned long long bb0 = pk2(b0.x, b0.y), bb1 = pk2(b0.z, b0.w);
        unsigned long long bb2 = pk2(b1.x, b1.y), bb3 = pk2(b1.z, b1.w);
        #pragma unroll
        for (int i = 0; i < 8; i++) {
            float a = As[(r0 + i) * SA2 + k];
            unsigned long long aa = pk2(a, a);
            fma2(acc[i][0], aa, bb0);
            fma2(acc[i][1], aa, bb1);
            fma2(acc[i][2], aa, bb2);
            fma2(acc[i][3], aa, bb3);
        }
    }
    #pragma unroll
    for (int i = 0; i < 8; i++) {
        int r = row0 + r0 + i;
        if (r < n_rows) {
            float2 p0 = up2(acc[i][0]), p1 = up2(acc[i][1]);
            float2 p2 = up2(acc[i][2]), p3 = up2(acc[i][3]);
            *(float4*)&out[(size_t)r * D + c0]     = make_float4(p0.x, p0.y, p1.x, p1.y);
            *(float4*)&out[(size_t)r * D + c0 + 4] = make_float4(p2.x, p2.y, p3.x, p3.y);
        }
    }
}

// ---------------------------------------------------------------------------
extern "C" void kernel_launch(void* const* d_in, const int* in_sizes, int n_in,
                              void* d_out, int out_size) {
    const float* feat_src    = (const float*)d_in[0];
    const float* feat_dst    = (const float*)d_in[1];
    const float* edge_weight = (const float*)d_in[2];
    const int*   src_idx     = (const int*)d_in[3];
    const int*   dst_idx     = (const int*)d_in[4];
    const float* weight_n    = (const float*)d_in[5];
    const float* weight_e    = (const float*)d_in[6];
    const float* query       = (const float*)d_in[7];
    const float* key_w       = (const float*)d_in[8];
    const float* att_w       = (const float*)d_in[9];
    const float* att_b       = (const float*)d_in[10];
    const float* out_w       = (const float*)d_in[11];
    const float* out_b       = (const float*)d_in[12];
    float* out = (float*)d_out;

    int n_nodes = in_sizes[0] / INC;
    int n_edges = in_sizes[3];

    const int SM1 = (128 * SA1 + INC * D) * 4;          // ~98.8 KB
    const int SM2 = (128 * SA2 + (INC + D) * D) * 4;    // ~148 KB
    cudaFuncSetAttribute(k_mm1, cudaFuncAttributeMaxDynamicSharedMemorySize, SM1);
    cudaFuncSetAttribute(k_mm2, cudaFuncAttributeMaxDynamicSharedMemorySize, SM2);

    int mm_blocks = (n_nodes + 127) / 128;
    k_pre<<<1, 256>>>(weight_n, weight_e, query, key_w, att_w, out_w);
    k_bounds<<<(n_edges + 1 + 255) / 256, 256>>>(dst_idx, n_nodes, n_edges);
    k_mm1<<<mm_blocks, 128, SM1>>>(feat_src, weight_n, n_nodes);
    k_qa<<<(n_nodes * 32 + 255) / 256, 256>>>(feat_dst, n_nodes);
    k_agg<<<(n_nodes * 16 + 255) / 256, 256>>>(src_idx, edge_weight, att_b, n_nodes);
    k_mm2<<<mm_blocks, 128, SM2>>>(feat_dst, out_w, out_b, out, n_nodes);
}

// round 3
// speedup vs baseline: 1.3947x; 1.3947x over previous
#include <cuda_runtime.h>
#include <math.h>

#define NN 50000
#define NE 800000
#define INC 128
#define D 64

// ---------------- scratch (static device globals; no allocation) ------------
__device__ float g_vq[INC];          // weight_n @ (query @ att_w[:d])
__device__ float g_tk[D];            // key_w @ att_w[d:2d]
__device__ float g_ce;               // weight_e[0,:] . att_w[2d:]
__device__ float g_W1[INC * D];      // weight_n @ out_w[:d]
__device__ float g_hsrc[(size_t)NN * D];
__device__ float g_qa[NN];
__device__ float g_ka[NN];
__device__ float g_agg[(size_t)NN * D];
__device__ int   g_start[NN + 1];

// ---------------- packed f32x2 helpers (Blackwell FFMA2) --------------------
__device__ __forceinline__ unsigned long long pk2(float lo, float hi) {
    unsigned long long r;
    asm("mov.b64 %0, {%1, %2};" : "=l"(r) : "f"(lo), "f"(hi));
    return r;
}
__device__ __forceinline__ void fma2(unsigned long long& d,
                                     unsigned long long a, unsigned long long b) {
    asm("fma.rn.f32x2 %0, %1, %2, %0;" : "+l"(d) : "l"(a), "l"(b));
}
__device__ __forceinline__ float2 up2(unsigned long long v) {
    float lo, hi;
    asm("mov.b64 {%0, %1}, %2;" : "=f"(lo), "=f"(hi) : "l"(v));
    return make_float2(lo, hi);
}

// ---------------- K_pre: fold small matrices (33 blocks) --------------------
// blocks 0..31: one element of W1 = weight_n @ out_w[:64] per thread
// block 32:     vq / tk / ce
__global__ void k_pre(const float* __restrict__ wn,
                      const float* __restrict__ we,
                      const float* __restrict__ query,
                      const float* __restrict__ key_w,
                      const float* __restrict__ att_w,
                      const float* __restrict__ out_w) {
    int t = threadIdx.x;
    if (blockIdx.x < 32) {
        int idx = blockIdx.x * 256 + t;      // 8192 outputs
        int k = idx >> 6, c = idx & 63;
        float s = 0.f;
        #pragma unroll 8
        for (int j = 0; j < D; j++) s += wn[k * D + j] * out_w[j * D + c];
        g_W1[idx] = s;
        return;
    }
    __shared__ float s_aw[3 * D];
    __shared__ float s_tq[D];
    for (int i = t; i < 3 * D; i += 256) s_aw[i] = att_w[i];
    __syncthreads();
    if (t < D) {
        float sq = 0.f, sk = 0.f;
        #pragma unroll 8
        for (int j = 0; j < D; j++) {
            sq += query[t * D + j] * s_aw[j];
            sk += key_w[t * D + j] * s_aw[D + j];
        }
        s_tq[t] = sq;
        g_tk[t] = sk;
    }
    if (t == 64) {
        float c = 0.f;
        for (int j = 0; j < D; j++) c += we[j] * s_aw[2 * D + j];
        g_ce = c;
    }
    __syncthreads();
    if (t < INC) {
        float vq = 0.f;
        #pragma unroll 8
        for (int i = 0; i < D; i++) vq += wn[t * D + i] * s_tq[i];
        g_vq[t] = vq;
    }
}

// ---------------- K_mm1: h_src = feat_src @ W_n  (+ ka epilogue) ------------
// 128-row tile, 256 threads, 4x8 micro-tile, packed f32x2 FMAs
#define SA1 129
__global__ void __launch_bounds__(256)
k_mm1(const float* __restrict__ feat, const float* __restrict__ wn, int n_rows) {
    extern __shared__ float sm[];
    float* As = sm;                  // 128 x SA1 (row-major, padded)
    float* Ws = sm + 128 * SA1;      // 128 x 64
    int row0 = blockIdx.x * 128;
    int t = threadIdx.x;
    float4* Ws4 = (float4*)Ws;
    const float4* wn4 = (const float4*)wn;
    for (int i = t; i < INC * D / 4; i += 256) Ws4[i] = wn4[i];
    int nr = n_rows - row0; if (nr > 128) nr = 128;
    const float4* f4 = (const float4*)(feat + (size_t)row0 * INC);
    for (int i = t; i < 128 * 32; i += 256) {
        int r = i >> 5, c4 = i & 31;
        float4 v = (r < nr) ? f4[i] : make_float4(0.f, 0.f, 0.f, 0.f);
        float* p = &As[r * SA1 + c4 * 4];
        p[0] = v.x; p[1] = v.y; p[2] = v.z; p[3] = v.w;
    }
    __syncthreads();
    int tx = t & 7, ty = t >> 3;     // ty 0..31
    int r0 = ty * 4;
    int cA = tx * 4, cB = 32 + tx * 4;
    unsigned long long acc[4][4] = {};   // [row][cA.lo,cA.hi,cB.lo,cB.hi]
    #pragma unroll 2
    for (int k = 0; k < INC; k++) {
        float4 bA = *(const float4*)&Ws[k * D + cA];
        float4 bB = *(const float4*)&Ws[k * D + cB];
        unsigned long long bb0 = pk2(bA.x, bA.y), bb1 = pk2(bA.z, bA.w);
        unsigned long long bb2 = pk2(bB.x, bB.y), bb3 = pk2(bB.z, bB.w);
        #pragma unroll
        for (int i = 0; i < 4; i++) {
            float a = As[(r0 + i) * SA1 + k];
            unsigned long long aa = pk2(a, a);
            fma2(acc[i][0], aa, bb0);
            fma2(acc[i][1], aa, bb1);
            fma2(acc[i][2], aa, bb2);
            fma2(acc[i][3], aa, bb3);
        }
    }
    float tkA[4], tkB[4];
    #pragma unroll
    for (int j = 0; j < 4; j++) { tkA[j] = g_tk[cA + j]; tkB[j] = g_tk[cB + j]; }
    #pragma unroll
    for (int i = 0; i < 4; i++) {
        int r = row0 + r0 + i;
        float2 p0 = up2(acc[i][0]), p1 = up2(acc[i][1]);
        float2 p2 = up2(acc[i][2]), p3 = up2(acc[i][3]);
        if (r < n_rows) {
            *(float4*)&g_hsrc[(size_t)r * D + cA] = make_float4(p0.x, p0.y, p1.x, p1.y);
            *(float4*)&g_hsrc[(size_t)r * D + cB] = make_float4(p2.x, p2.y, p3.x, p3.y);
        }
        float ka = p0.x * tkA[0] + p0.y * tkA[1] + p1.x * tkA[2] + p1.y * tkA[3]
                 + p2.x * tkB[0] + p2.y * tkB[1] + p3.x * tkB[2] + p3.y * tkB[3];
        ka += __shfl_xor_sync(0xffffffffu, ka, 1);
        ka += __shfl_xor_sync(0xffffffffu, ka, 2);
        ka += __shfl_xor_sync(0xffffffffu, ka, 4);
        if (tx == 0 && r < n_rows) g_ka[r] = ka;
    }
}

// ---------------- K_qa: qa = feat_dst . vq  (warp per node, float4) ---------
__global__ void k_qa(const float* __restrict__ feat_dst, int n_nodes) {
    int w = (blockIdx.x * blockDim.x + threadIdx.x) >> 5;
    int lane = threadIdx.x & 31;
    if (w >= n_nodes) return;
    float4 f = ((const float4*)(feat_dst + (size_t)w * INC))[lane];
    float4 v = ((const float4*)g_vq)[lane];
    float qa = f.x * v.x + f.y * v.y + f.z * v.z + f.w * v.w;
    #pragma unroll
    for (int o = 16; o > 0; o >>= 1) qa += __shfl_xor_sync(0xffffffffu, qa, o);
    if (lane == 0) g_qa[w] = qa;
}

// ---------------- K_bounds: segment starts via scatter over edges -----------
__global__ void k_bounds(const int* __restrict__ dst, int n_nodes, int n_edges) {
    int e = blockIdx.x * blockDim.x + threadIdx.x;
    if (e > n_edges) return;
    int d1 = (e < n_edges) ? dst[e] : n_nodes;
    int d0 = (e > 0) ? dst[e - 1] : -1;
    for (int n = d0 + 1; n <= d1; n++) g_start[n] = e;
}

// ---------------- K_agg: fused softmax + message sum (warp per node) --------
// no max-subtraction (logits O(1)); halves process even/odd edges for 2x MLP
__global__ void k_agg(const int* __restrict__ src_idx,
                      const float* __restrict__ ew,
                      const float* __restrict__ att_b, int n_nodes) {
    int w = (blockIdx.x * blockDim.x + threadIdx.x) >> 5;
    int lane = threadIdx.x & 31;
    if (w >= n_nodes) return;
    int sl = lane & 15, half = lane >> 4;
    int e0 = g_start[w], e1 = g_start[w + 1];
    if (e0 == e1) {
        if (lane < 16) *(float4*)&g_agg[(size_t)w * D + 4 * sl] =
            make_float4(0.f, 0.f, 0.f, 0.f);
        return;
    }
    float qn = g_qa[w] + att_b[0];
    float ce = g_ce;
    // pass 1: total exp-sum (all 32 lanes strided)
    float s = 0.f;
    for (int e = e0 + lane; e < e1; e += 32) {
        float x = qn + g_ka[src_idx[e]] + ew[e] * ce;
        x = (x >= 0.f) ? x : 0.2f * x;
        s += __expf(x);
    }
    #pragma unroll
    for (int o = 16; o > 0; o >>= 1) s += __shfl_xor_sync(0xffffffffu, s, o);
    // pass 2: weighted sum; half 0 takes even edges, half 1 odd edges
    float4 acc = make_float4(0.f, 0.f, 0.f, 0.f);
    for (int e = e0 + half; e < e1; e += 2) {
        int si = src_idx[e];                         // uniform within half
        float x = qn + g_ka[si] + ew[e] * ce;
        x = (x >= 0.f) ? x : 0.2f * x;
        float al = __expf(x);
        float4 h = *(const float4*)&g_hsrc[(size_t)si * D + 4 * sl];
        acc.x += al * h.x; acc.y += al * h.y; acc.z += al * h.z; acc.w += al * h.w;
    }
    acc.x += __shfl_xor_sync(0xffffffffu, acc.x, 16);
    acc.y += __shfl_xor_sync(0xffffffffu, acc.y, 16);
    acc.z += __shfl_xor_sync(0xffffffffu, acc.z, 16);
    acc.w += __shfl_xor_sync(0xffffffffu, acc.w, 16);
    float inv = 1.f / (s + 1e-16f);
    if (lane < 16)
        *(float4*)&g_agg[(size_t)w * D + 4 * sl] =
            make_float4(acc.x * inv, acc.y * inv, acc.z * inv, acc.w * inv);
}

// ---------------- K_mm2: out = feat_dst@W1 + agg@out_w[64:] + b -------------
// two K phases (128 then 64) sharing one As buffer; 256 threads, 4x8 micro
__global__ void __launch_bounds__(256)
k_mm2(const float* __restrict__ feat_dst, const float* __restrict__ out_w,
      const float* __restrict__ out_b, float* __restrict__ out, int n_rows) {
    extern __shared__ float sm[];
    float* As = sm;                  // 128 x SA1
    float* Ws = sm + 128 * SA1;      // 128 x 64 (reused per phase)
    int row0 = blockIdx.x * 128;
    int t = threadIdx.x;
    int nr = n_rows - row0; if (nr > 128) nr = 128;
    float4* Ws4 = (float4*)Ws;
    // phase 1: feat_dst (K=128) x W1
    const float4* w14 = (const float4*)g_W1;
    for (int i = t; i < INC * D / 4; i += 256) Ws4[i] = w14[i];
    const float4* f4 = (const float4*)(feat_dst + (size_t)row0 * INC);
    for (int i = t; i < 128 * 32; i += 256) {
        int r = i >> 5, c4 = i & 31;
        float4 v = (r < nr) ? f4[i] : make_float4(0.f, 0.f, 0.f, 0.f);
        float* p = &As[r * SA1 + c4 * 4];
        p[0] = v.x; p[1] = v.y; p[2] = v.z; p[3] = v.w;
    }
    __syncthreads();
    int tx = t & 7, ty = t >> 3;
    int r0 = ty * 4;
    int cA = tx * 4, cB = 32 + tx * 4;
    float4 obA = *(const float4*)&out_b[cA];
    float4 obB = *(const float4*)&out_b[cB];
    unsigned long long acc[4][4];
    #pragma unroll
    for (int i = 0; i < 4; i++) {
        acc[i][0] = pk2(obA.x, obA.y); acc[i][1] = pk2(obA.z, obA.w);
        acc[i][2] = pk2(obB.x, obB.y); acc[i][3] = pk2(obB.z, obB.w);
    }
    #pragma unroll 2
    for (int k = 0; k < INC; k++) {
        float4 bA = *(const float4*)&Ws[k * D + cA];
        float4 bB = *(const float4*)&Ws[k * D + cB];
        unsigned long long bb0 = pk2(bA.x, bA.y), bb1 = pk2(bA.z, bA.w);
        unsigned long long bb2 = pk2(bB.x, bB.y), bb3 = pk2(bB.z, bB.w);
        #pragma unroll
        for (int i = 0; i < 4; i++) {
            float a = As[(r0 + i) * SA1 + k];
            unsigned long long aa = pk2(a, a);
            fma2(acc[i][0], aa, bb0);
            fma2(acc[i][1], aa, bb1);
            fma2(acc[i][2], aa, bb2);
            fma2(acc[i][3], aa, bb3);
        }
    }
    __syncthreads();
    // phase 2: agg (K=64) x out_w[64:]
    const float4* ow4 = (const float4*)(out_w + (size_t)D * D);
    for (int i = t; i < D * D / 4; i += 256) Ws4[i] = ow4[i];
    const float4* a4 = (const float4*)(g_agg + (size_t)row0 * D);
    for (int i = t; i < 128 * 16; i += 256) {
        int r = i >> 4, c4 = i & 15;
        float4 v = (r < nr) ? a4[i] : make_float4(0.f, 0.f, 0.f, 0.f);
        float* p = &As[r * SA1 + c4 * 4];
        p[0] = v.x; p[1] = v.y; p[2] = v.z; p[3] = v.w;
    }
    __syncthreads();
    #pragma unroll 2
    for (int k = 0; k < D; k++) {
        float4 bA = *(const float4*)&Ws[k * D + cA];
        float4 bB = *(const float4*)&Ws[k * D + cB];
        unsigned long long bb0 = pk2(bA.x, bA.y), bb1 = pk2(bA.z, bA.w);
        unsigned long long bb2 = pk2(bB.x, bB.y), bb3 = pk2(bB.z, bB.w);
        #pragma unroll
        for (int i = 0; i < 4; i++) {
            float a = As[(r0 + i) * SA1 + k];
            unsigned long long aa = pk2(a, a);
            fma2(acc[i][0], aa, bb0);
            fma2(acc[i][1], aa, bb1);
            fma2(acc[i][2], aa, bb2);
            fma2(acc[i][3], aa, bb3);
        }
    }
    #pragma unroll
    for (int i = 0; i < 4; i++) {
        int r = row0 + r0 + i;
        if (r < n_rows) {
            float2 p0 = up2(acc[i][0]), p1 = up2(acc[i][1]);
            float2 p2 = up2(acc[i][2]), p3 = up2(acc[i][3]);
            *(float4*)&out[(size_t)r * D + cA] = make_float4(p0.x, p0.y, p1.x, p1.y);
            *(float4*)&out[(size_t)r * D + cB] = make_float4(p2.x, p2.y, p3.x, p3.y);
        }
    }
}

// ---------------------------------------------------------------------------
extern "C" void kernel_launch(void* const* d_in, const int* in_sizes, int n_in,
                              void* d_out, int out_size) {
    const float* feat_src    = (const float*)d_in[0];
    const float* feat_dst    = (const float*)d_in[1];
    const float* edge_weight = (const float*)d_in[2];
    const int*   src_idx     = (const int*)d_in[3];
    const int*   dst_idx     = (const int*)d_in[4];
    const float* weight_n    = (const float*)d_in[5];
    const float* weight_e    = (const float*)d_in[6];
    const float* query       = (const float*)d_in[7];
    const float* key_w       = (const float*)d_in[8];
    const float* att_w       = (const float*)d_in[9];
    const float* att_b       = (const float*)d_in[10];
    const float* out_w       = (const float*)d_in[11];
    const float* out_b       = (const float*)d_in[12];
    float* out = (float*)d_out;

    int n_nodes = in_sizes[0] / INC;
    int n_edges = in_sizes[3];

    const int SMM = (128 * SA1 + INC * D) * 4;   // 98816 B -> 2 CTAs/SM
    cudaFuncSetAttribute(k_mm1, cudaFuncAttributeMaxDynamicSharedMemorySize, SMM);
    cudaFuncSetAttribute(k_mm2, cudaFuncAttributeMaxDynamicSharedMemorySize, SMM);

    int mm_blocks = (n_nodes + 127) / 128;
    k_pre<<<33, 256>>>(weight_n, weight_e, query, key_w, att_w, out_w);
    k_bounds<<<(n_edges + 1 + 255) / 256, 256>>>(dst_idx, n_nodes, n_edges);
    k_mm1<<<mm_blocks, 256, SMM>>>(feat_src, weight_n, n_nodes);
    k_qa<<<(n_nodes * 32 + 255) / 256, 256>>>(feat_dst, n_nodes);
    k_agg<<<(n_nodes * 32 + 255) / 256, 256>>>(src_idx, edge_weight, att_b, n_nodes);
    k_mm2<<<mm_blocks, 256, SMM>>>(feat_dst, out_w, out_b, out, n_nodes);
}

// round 4
// speedup vs baseline: 1.5180x; 1.0884x over previous
#include <cuda_runtime.h>
#include <math.h>

#define NN 50000
#define NE 800000
#define INC 128
#define D 64

// ---------------- scratch (static device globals; no allocation) ------------
__device__ float g_vq[INC];          // weight_n @ (query @ att_w[:d])
__device__ float g_tk[D];            // key_w @ att_w[d:2d]
__device__ float g_ce;               // weight_e[0,:] . att_w[2d:]
__device__ float g_W1[INC * D];      // weight_n @ out_w[:d]
__device__ float g_hsrc[(size_t)NN * D];
__device__ float g_ka[NN];
__device__ float g_agg[(size_t)NN * D];
__device__ int   g_start[NN + 1];

// ---------------- packed f32x2 helpers (Blackwell FFMA2) --------------------
__device__ __forceinline__ unsigned long long pk2(float lo, float hi) {
    unsigned long long r;
    asm("mov.b64 %0, {%1, %2};" : "=l"(r) : "f"(lo), "f"(hi));
    return r;
}
__device__ __forceinline__ void fma2(unsigned long long& d,
                                     unsigned long long a, unsigned long long b) {
    asm("fma.rn.f32x2 %0, %1, %2, %0;" : "+l"(d) : "l"(a), "l"(b));
}
__device__ __forceinline__ float2 up2(unsigned long long v) {
    float lo, hi;
    asm("mov.b64 {%0, %1}, %2;" : "=f"(lo), "=f"(hi) : "l"(v));
    return make_float2(lo, hi);
}

// ---------------- K_prep: fold small mats + segment bounds (one launch) -----
// blocks [0,32):  W1 = weight_n @ out_w[:64]       (one element per thread)
// block  32:      vq / tk / ce
// blocks [33,..): segment starts via scatter over edges
__global__ void k_prep(const float* __restrict__ wn,
                       const float* __restrict__ we,
                       const float* __restrict__ query,
                       const float* __restrict__ key_w,
                       const float* __restrict__ att_w,
                       const float* __restrict__ out_w,
                       const int* __restrict__ dst,
                       int n_nodes, int n_edges) {
    int t = threadIdx.x;
    if (blockIdx.x < 32) {
        int idx = blockIdx.x * 256 + t;      // 8192 outputs
        int k = idx >> 6, c = idx & 63;
        float s = 0.f;
        #pragma unroll 8
        for (int j = 0; j < D; j++) s += wn[k * D + j] * out_w[j * D + c];
        g_W1[idx] = s;
        return;
    }
    if (blockIdx.x > 32) {
        int e = (blockIdx.x - 33) * 256 + t;
        if (e > n_edges) return;
        int d1 = (e < n_edges) ? dst[e] : n_nodes;
        int d0 = (e > 0) ? dst[e - 1] : -1;
        for (int n = d0 + 1; n <= d1; n++) g_start[n] = e;
        return;
    }
    __shared__ float s_aw[3 * D];
    __shared__ float s_tq[D];
    for (int i = t; i < 3 * D; i += 256) s_aw[i] = att_w[i];
    __syncthreads();
    if (t < D) {
        float sq = 0.f, sk = 0.f;
        #pragma unroll 8
        for (int j = 0; j < D; j++) {
            sq += query[t * D + j] * s_aw[j];
            sk += key_w[t * D + j] * s_aw[D + j];
        }
        s_tq[t] = sq;
        g_tk[t] = sk;
    }
    if (t == 64) {
        float c = 0.f;
        for (int j = 0; j < D; j++) c += we[j] * s_aw[2 * D + j];
        g_ce = c;
    }
    __syncthreads();
    if (t < INC) {
        float vq = 0.f;
        #pragma unroll 8
        for (int i = 0; i < D; i++) vq += wn[t * D + i] * s_tq[i];
        g_vq[t] = vq;
    }
}

// ---------------- K_mm1: h_src = feat_src @ W_n  (+ ka epilogue) ------------
// 128-row tile, 256 threads, 4x8 micro-tile, packed f32x2 FMAs
#define SA1 129
__global__ void __launch_bounds__(256)
k_mm1(const float* __restrict__ feat, const float* __restrict__ wn, int n_rows) {
    extern __shared__ float sm[];
    float* As = sm;                  // 128 x SA1 (row-major, padded)
    float* Ws = sm + 128 * SA1;      // 128 x 64
    int row0 = blockIdx.x * 128;
    int t = threadIdx.x;
    float4* Ws4 = (float4*)Ws;
    const float4* wn4 = (const float4*)wn;
    for (int i = t; i < INC * D / 4; i += 256) Ws4[i] = wn4[i];
    int nr = n_rows - row0; if (nr > 128) nr = 128;
    const float4* f4 = (const float4*)(feat + (size_t)row0 * INC);
    for (int i = t; i < 128 * 32; i += 256) {
        int r = i >> 5, c4 = i & 31;
        float4 v = (r < nr) ? f4[i] : make_float4(0.f, 0.f, 0.f, 0.f);
        float* p = &As[r * SA1 + c4 * 4];
        p[0] = v.x; p[1] = v.y; p[2] = v.z; p[3] = v.w;
    }
    __syncthreads();
    int tx = t & 7, ty = t >> 3;     // ty 0..31
    int r0 = ty * 4;
    int cA = tx * 4, cB = 32 + tx * 4;
    unsigned long long acc[4][4] = {};
    #pragma unroll 2
    for (int k = 0; k < INC; k++) {
        float4 bA = *(const float4*)&Ws[k * D + cA];
        float4 bB = *(const float4*)&Ws[k * D + cB];
        unsigned long long bb0 = pk2(bA.x, bA.y), bb1 = pk2(bA.z, bA.w);
        unsigned long long bb2 = pk2(bB.x, bB.y), bb3 = pk2(bB.z, bB.w);
        #pragma unroll
        for (int i = 0; i < 4; i++) {
            float a = As[(r0 + i) * SA1 + k];
            unsigned long long aa = pk2(a, a);
            fma2(acc[i][0], aa, bb0);
            fma2(acc[i][1], aa, bb1);
            fma2(acc[i][2], aa, bb2);
            fma2(acc[i][3], aa, bb3);
        }
    }
    float tkA[4], tkB[4];
    #pragma unroll
    for (int j = 0; j < 4; j++) { tkA[j] = g_tk[cA + j]; tkB[j] = g_tk[cB + j]; }
    #pragma unroll
    for (int i = 0; i < 4; i++) {
        int r = row0 + r0 + i;
        float2 p0 = up2(acc[i][0]), p1 = up2(acc[i][1]);
        float2 p2 = up2(acc[i][2]), p3 = up2(acc[i][3]);
        if (r < n_rows) {
            *(float4*)&g_hsrc[(size_t)r * D + cA] = make_float4(p0.x, p0.y, p1.x, p1.y);
            *(float4*)&g_hsrc[(size_t)r * D + cB] = make_float4(p2.x, p2.y, p3.x, p3.y);
        }
        float ka = p0.x * tkA[0] + p0.y * tkA[1] + p1.x * tkA[2] + p1.y * tkA[3]
                 + p2.x * tkB[0] + p2.y * tkB[1] + p3.x * tkB[2] + p3.y * tkB[3];
        ka += __shfl_xor_sync(0xffffffffu, ka, 1);
        ka += __shfl_xor_sync(0xffffffffu, ka, 2);
        ka += __shfl_xor_sync(0xffffffffu, ka, 4);
        if (tx == 0 && r < n_rows) g_ka[r] = ka;
    }
}

// ---------------- K_agg: qa + softmax + message sum, ONE pass (warp/node) ---
// agg = (sum_e w_e h_e) / (sum_e w_e): accumulate both in the same loop.
// halves of the warp take even/odd edges (2x MLP), each lane holds 4 channels.
__global__ void k_agg(const int* __restrict__ src_idx,
                      const float* __restrict__ ew,
                      const float* __restrict__ feat_dst,
                      const float* __restrict__ att_b, int n_nodes) {
    int w = (blockIdx.x * blockDim.x + threadIdx.x) >> 5;
    int lane = threadIdx.x & 31;
    if (w >= n_nodes) return;
    int sl = lane & 15, half = lane >> 4;
    int e0 = g_start[w], e1 = g_start[w + 1];
    if (e0 == e1) {
        if (lane < 16) *(float4*)&g_agg[(size_t)w * D + 4 * sl] =
            make_float4(0.f, 0.f, 0.f, 0.f);
        return;
    }
    // qa = feat_dst[w] . vq  (inline, coalesced)
    float4 f = ((const float4*)(feat_dst + (size_t)w * INC))[lane];
    float4 v = ((const float4*)g_vq)[lane];
    float qa = f.x * v.x + f.y * v.y + f.z * v.z + f.w * v.w;
    #pragma unroll
    for (int o = 16; o > 0; o >>= 1) qa += __shfl_xor_sync(0xffffffffu, qa, o);
    float qn = qa + att_b[0];
    float ce = g_ce;
    // single fused pass: s and weighted sum together
    float s = 0.f;
    float4 acc = make_float4(0.f, 0.f, 0.f, 0.f);
    for (int e = e0 + half; e < e1; e += 2) {
        int si = src_idx[e];                         // broadcast within half
        float x = qn + g_ka[si] + ew[e] * ce;
        x = (x >= 0.f) ? x : 0.2f * x;
        float al = __expf(x);
        s += al;
        float4 h = *(const float4*)&g_hsrc[(size_t)si * D + 4 * sl];
        acc.x += al * h.x; acc.y += al * h.y; acc.z += al * h.z; acc.w += al * h.w;
    }
    s += __shfl_xor_sync(0xffffffffu, s, 16);
    acc.x += __shfl_xor_sync(0xffffffffu, acc.x, 16);
    acc.y += __shfl_xor_sync(0xffffffffu, acc.y, 16);
    acc.z += __shfl_xor_sync(0xffffffffu, acc.z, 16);
    acc.w += __shfl_xor_sync(0xffffffffu, acc.w, 16);
    float inv = 1.f / (s + 1e-16f);
    if (lane < 16)
        *(float4*)&g_agg[(size_t)w * D + 4 * sl] =
            make_float4(acc.x * inv, acc.y * inv, acc.z * inv, acc.w * inv);
}

// ---------------- K_mm2: out = feat_dst@W1 + agg@out_w[64:] + b -------------
// two K phases (128 then 64) sharing one As buffer; 256 threads, 4x8 micro
__global__ void __launch_bounds__(256)
k_mm2(const float* __restrict__ feat_dst, const float* __restrict__ out_w,
      const float* __restrict__ out_b, float* __restrict__ out, int n_rows) {
    extern __shared__ float sm[];
    float* As = sm;                  // 128 x SA1
    float* Ws = sm + 128 * SA1;      // 128 x 64 (reused per phase)
    int row0 = blockIdx.x * 128;
    int t = threadIdx.x;
    int nr = n_rows - row0; if (nr > 128) nr = 128;
    float4* Ws4 = (float4*)Ws;
    // phase 1: feat_dst (K=128) x W1
    const float4* w14 = (const float4*)g_W1;
    for (int i = t; i < INC * D / 4; i += 256) Ws4[i] = w14[i];
    const float4* f4 = (const float4*)(feat_dst + (size_t)row0 * INC);
    for (int i = t; i < 128 * 32; i += 256) {
        int r = i >> 5, c4 = i & 31;
        float4 v = (r < nr) ? f4[i] : make_float4(0.f, 0.f, 0.f, 0.f);
        float* p = &As[r * SA1 + c4 * 4];
        p[0] = v.x; p[1] = v.y; p[2] = v.z; p[3] = v.w;
    }
    __syncthreads();
    int tx = t & 7, ty = t >> 3;
    int r0 = ty * 4;
    int cA = tx * 4, cB = 32 + tx * 4;
    float4 obA = *(const float4*)&out_b[cA];
    float4 obB = *(const float4*)&out_b[cB];
    unsigned long long acc[4][4];
    #pragma unroll
    for (int i = 0; i < 4; i++) {
        acc[i][0] = pk2(obA.x, obA.y); acc[i][1] = pk2(obA.z, obA.w);
        acc[i][2] = pk2(obB.x, obB.y); acc[i][3] = pk2(obB.z, obB.w);
    }
    #pragma unroll 2
    for (int k = 0; k < INC; k++) {
        float4 bA = *(const float4*)&Ws[k * D + cA];
        float4 bB = *(const float4*)&Ws[k * D + cB];
        unsigned long long bb0 = pk2(bA.x, bA.y), bb1 = pk2(bA.z, bA.w);
        unsigned long long bb2 = pk2(bB.x, bB.y), bb3 = pk2(bB.z, bB.w);
        #pragma unroll
        for (int i = 0; i < 4; i++) {
            float a = As[(r0 + i) * SA1 + k];
            unsigned long long aa = pk2(a, a);
            fma2(acc[i][0], aa, bb0);
            fma2(acc[i][1], aa, bb1);
            fma2(acc[i][2], aa, bb2);
            fma2(acc[i][3], aa, bb3);
        }
    }
    __syncthreads();
    // phase 2: agg (K=64) x out_w[64:]
    const float4* ow4 = (const float4*)(out_w + (size_t)D * D);
    for (int i = t; i < D * D / 4; i += 256) Ws4[i] = ow4[i];
    const float4* a4 = (const float4*)(g_agg + (size_t)row0 * D);
    for (int i = t; i < 128 * 16; i += 256) {
        int r = i >> 4, c4 = i & 15;
        float4 v = (r < nr) ? a4[i] : make_float4(0.f, 0.f, 0.f, 0.f);
        float* p = &As[r * SA1 + c4 * 4];
        p[0] = v.x; p[1] = v.y; p[2] = v.z; p[3] = v.w;
    }
    __syncthreads();
    #pragma unroll 2
    for (int k = 0; k < D; k++) {
        float4 bA = *(const float4*)&Ws[k * D + cA];
        float4 bB = *(const float4*)&Ws[k * D + cB];
        unsigned long long bb0 = pk2(bA.x, bA.y), bb1 = pk2(bA.z, bA.w);
        unsigned long long bb2 = pk2(bB.x, bB.y), bb3 = pk2(bB.z, bB.w);
        #pragma unroll
        for (int i = 0; i < 4; i++) {
            float a = As[(r0 + i) * SA1 + k];
            unsigned long long aa = pk2(a, a);
            fma2(acc[i][0], aa, bb0);
            fma2(acc[i][1], aa, bb1);
            fma2(acc[i][2], aa, bb2);
            fma2(acc[i][3], aa, bb3);
        }
    }
    #pragma unroll
    for (int i = 0; i < 4; i++) {
        int r = row0 + r0 + i;
        if (r < n_rows) {
            float2 p0 = up2(acc[i][0]), p1 = up2(acc[i][1]);
            float2 p2 = up2(acc[i][2]), p3 = up2(acc[i][3]);
            *(float4*)&out[(size_t)r * D + cA] = make_float4(p0.x, p0.y, p1.x, p1.y);
            *(float4*)&out[(size_t)r * D + cB] = make_float4(p2.x, p2.y, p3.x, p3.y);
        }
    }
}

// ---------------------------------------------------------------------------
extern "C" void kernel_launch(void* const* d_in, const int* in_sizes, int n_in,
                              void* d_out, int out_size) {
    const float* feat_src    = (const float*)d_in[0];
    const float* feat_dst    = (const float*)d_in[1];
    const float* edge_weight = (const float*)d_in[2];
    const int*   src_idx     = (const int*)d_in[3];
    const int*   dst_idx     = (const int*)d_in[4];
    const float* weight_n    = (const float*)d_in[5];
    const float* weight_e    = (const float*)d_in[6];
    const float* query       = (const float*)d_in[7];
    const float* key_w       = (const float*)d_in[8];
    const float* att_w       = (const float*)d_in[9];
    const float* att_b       = (const float*)d_in[10];
    const float* out_w       = (const float*)d_in[11];
    const float* out_b       = (const float*)d_in[12];
    float* out = (float*)d_out;

    int n_nodes = in_sizes[0] / INC;
    int n_edges = in_sizes[3];

    const int SMM = (128 * SA1 + INC * D) * 4;   // 98816 B -> 2 CTAs/SM
    cudaFuncSetAttribute(k_mm1, cudaFuncAttributeMaxDynamicSharedMemorySize, SMM);
    cudaFuncSetAttribute(k_mm2, cudaFuncAttributeMaxDynamicSharedMemorySize, SMM);

    int mm_blocks = (n_nodes + 127) / 128;
    int prep_blocks = 33 + (n_edges + 1 + 255) / 256;
    k_prep<<<prep_blocks, 256>>>(weight_n, weight_e, query, key_w, att_w,
                                 out_w, dst_idx, n_nodes, n_edges);
    k_mm1<<<mm_blocks, 256, SMM>>>(feat_src, weight_n, n_nodes);
    k_agg<<<(n_nodes * 32 + 255) / 256, 256>>>(src_idx, edge_weight, feat_dst,
                                               att_b, n_nodes);
    k_mm2<<<mm_blocks, 256, SMM>>>(feat_dst, out_w, out_b, out, n_nodes);
}

// round 8
// speedup vs baseline: 1.7448x; 1.1495x over previous
#include <cuda_runtime.h>
#include <math.h>
#include <cstdint>

#define NN 50000
#define NE 800000
#define INC 128
#define D 64

// ---------------- scratch (static device globals; no allocation) ------------
__device__ float g_vq[INC];          // weight_n @ (query @ att_w[:d])
__device__ float g_tk[D];            // key_w @ att_w[d:2d]
__device__ float g_ce;               // weight_e[0,:] . att_w[2d:]
__device__ float g_W1[INC * D];      // weight_n @ out_w[:d]
__device__ float g_hsrc[(size_t)NN * D];
__device__ float g_ka[NN];
__device__ float g_agg[(size_t)NN * D];
__device__ int   g_start[NN + 1];

// ---------------- packed f32x2 helpers (Blackwell FFMA2) --------------------
__device__ __forceinline__ unsigned long long pk2(float lo, float hi) {
    unsigned long long r;
    asm("mov.b64 %0, {%1, %2};" : "=l"(r) : "f"(lo), "f"(hi));
    return r;
}
__device__ __forceinline__ void fma2(unsigned long long& d,
                                     unsigned long long a, unsigned long long b) {
    asm("fma.rn.f32x2 %0, %1, %2, %0;" : "+l"(d) : "l"(a), "l"(b));
}
__device__ __forceinline__ float2 up2(unsigned long long v) {
    float lo, hi;
    asm("mov.b64 {%0, %1}, %2;" : "=f"(lo), "=f"(hi) : "l"(v));
    return make_float2(lo, hi);
}

// ---------------- K_prep: fold small mats + segment bounds (one launch) -----
__global__ void k_prep(const float* __restrict__ wn,
                       const float* __restrict__ we,
                       const float* __restrict__ query,
                       const float* __restrict__ key_w,
                       const float* __restrict__ att_w,
                       const float* __restrict__ out_w,
                       const int* __restrict__ dst,
                       int n_nodes, int n_edges) {
    int t = threadIdx.x;
    if (blockIdx.x < 32) {
        int idx = blockIdx.x * 256 + t;      // 8192 outputs of W1
        int k = idx >> 6, c = idx & 63;
        float s = 0.f;
        #pragma unroll 8
        for (int j = 0; j < D; j++) s += wn[k * D + j] * out_w[j * D + c];
        g_W1[idx] = s;
        return;
    }
    if (blockIdx.x > 32) {
        int e = (blockIdx.x - 33) * 256 + t;
        if (e > n_edges) return;
        int d1 = (e < n_edges) ? dst[e] : n_nodes;
        int d0 = (e > 0) ? dst[e - 1] : -1;
        for (int n = d0 + 1; n <= d1; n++) g_start[n] = e;
        return;
    }
    __shared__ float s_aw[3 * D];
    __shared__ float s_tq[D];
    for (int i = t; i < 3 * D; i += 256) s_aw[i] = att_w[i];
    __syncthreads();
    if (t < D) {
        float sq = 0.f, sk = 0.f;
        #pragma unroll 8
        for (int j = 0; j < D; j++) {
            sq += query[t * D + j] * s_aw[j];
            sk += key_w[t * D + j] * s_aw[D + j];
        }
        s_tq[t] = sq;
        g_tk[t] = sk;
    }
    if (t == 64) {
        float c = 0.f;
        for (int j = 0; j < D; j++) c += we[j] * s_aw[2 * D + j];
        g_ce = c;
    }
    __syncthreads();
    if (t < INC) {
        float vq = 0.f;
        #pragma unroll 8
        for (int i = 0; i < D; i++) vq += wn[t * D + i] * s_tq[i];
        g_vq[t] = vq;
    }
}

// ---------------- K_mm1: h_src = feat_src @ W_n  (+ ka epilogue) ------------
// 128 rows/block, 256 threads, 4x8 micro-tile.
// A read straight from gmem (8-lane broadcast), B pre-packed f32x2 in smem.
#define SMW1 (INC * 32 * 8)          // 32 KB of packed pairs
__global__ void __launch_bounds__(256)
k_mm1(const float* __restrict__ feat, const float* __restrict__ wn, int n_rows) {
    extern __shared__ unsigned long long Ws2[];   // [k][32 pairs]
    int t = threadIdx.x;
    const float4* wn4 = (const float4*)wn;
    for (int i = t; i < INC * 16; i += 256) {
        float4 v = wn4[i];
        int k = i >> 4, c4 = i & 15;
        Ws2[k * 32 + c4 * 2]     = pk2(v.x, v.y);
        Ws2[k * 32 + c4 * 2 + 1] = pk2(v.z, v.w);
    }
    __syncthreads();
    int row0 = blockIdx.x * 128;
    int tx = t & 7, ty = t >> 3;
    int r0 = row0 + ty * 4;
    const float4* rp[4];
    #pragma unroll
    for (int i = 0; i < 4; i++) {
        int r = r0 + i; if (r > n_rows - 1) r = n_rows - 1;
        rp[i] = (const float4*)(feat + (size_t)r * INC);
    }
    int cA = tx * 4, cB = 32 + tx * 4;
    unsigned long long acc[4][4] = {};
    for (int kk = 0; kk < 32; kk++) {
        float4 av[4];
        #pragma unroll
        for (int i = 0; i < 4; i++) av[i] = __ldg(&rp[i][kk]);
        #pragma unroll
        for (int j = 0; j < 4; j++) {
            int k = kk * 4 + j;
            ulonglong2 bA = *(const ulonglong2*)&Ws2[k * 32 + tx * 2];
            ulonglong2 bB = *(const ulonglong2*)&Ws2[k * 32 + 16 + tx * 2];
            #pragma unroll
            for (int i = 0; i < 4; i++) {
                float a = (j == 0) ? av[i].x : (j == 1) ? av[i].y
                        : (j == 2) ? av[i].z : av[i].w;
                unsigned long long aa = pk2(a, a);
                fma2(acc[i][0], aa, bA.x);
                fma2(acc[i][1], aa, bA.y);
                fma2(acc[i][2], aa, bB.x);
                fma2(acc[i][3], aa, bB.y);
            }
        }
    }
    float tkA[4], tkB[4];
    #pragma unroll
    for (int j = 0; j < 4; j++) { tkA[j] = g_tk[cA + j]; tkB[j] = g_tk[cB + j]; }
    #pragma unroll
    for (int i = 0; i < 4; i++) {
        int r = r0 + i;
        float2 p0 = up2(acc[i][0]), p1 = up2(acc[i][1]);
        float2 p2 = up2(acc[i][2]), p3 = up2(acc[i][3]);
        if (r < n_rows) {
            *(float4*)&g_hsrc[(size_t)r * D + cA] = make_float4(p0.x, p0.y, p1.x, p1.y);
            *(float4*)&g_hsrc[(size_t)r * D + cB] = make_float4(p2.x, p2.y, p3.x, p3.y);
        }
        float ka = p0.x * tkA[0] + p0.y * tkA[1] + p1.x * tkA[2] + p1.y * tkA[3]
                 + p2.x * tkB[0] + p2.y * tkB[1] + p3.x * tkB[2] + p3.y * tkB[3];
        ka += __shfl_xor_sync(0xffffffffu, ka, 1);
        ka += __shfl_xor_sync(0xffffffffu, ka, 2);
        ka += __shfl_xor_sync(0xffffffffu, ka, 4);
        if (tx == 0 && r < n_rows) g_ka[r] = ka;
    }
}

// ---------------- K_agg: qa + softmax + message sum, ONE pass (warp/node) ---
__global__ void k_agg(const int* __restrict__ src_idx,
                      const float* __restrict__ ew,
                      const float* __restrict__ feat_dst,
                      const float* __restrict__ att_b, int n_nodes) {
    int w = (blockIdx.x * blockDim.x + threadIdx.x) >> 5;
    int lane = threadIdx.x & 31;
    if (w >= n_nodes) return;
    int sl = lane & 15, half = lane >> 4;
    int e0 = g_start[w], e1 = g_start[w + 1];
    if (e0 == e1) {
        if (lane < 16) *(float4*)&g_agg[(size_t)w * D + 4 * sl] =
            make_float4(0.f, 0.f, 0.f, 0.f);
        return;
    }
    float4 f = ((const float4*)(feat_dst + (size_t)w * INC))[lane];
    float4 v = ((const float4*)g_vq)[lane];
    float qa = f.x * v.x + f.y * v.y + f.z * v.z + f.w * v.w;
    #pragma unroll
    for (int o = 16; o > 0; o >>= 1) qa += __shfl_xor_sync(0xffffffffu, qa, o);
    float qn = qa + att_b[0];
    float ce = g_ce;
    float s = 0.f;
    float4 acc = make_float4(0.f, 0.f, 0.f, 0.f);
    for (int e = e0 + half; e < e1; e += 2) {
        int si = src_idx[e];
        float x = qn + g_ka[si] + ew[e] * ce;
        x = (x >= 0.f) ? x : 0.2f * x;
        float al = __expf(x);
        s += al;
        float4 h = *(const float4*)&g_hsrc[(size_t)si * D + 4 * sl];
        acc.x += al * h.x; acc.y += al * h.y; acc.z += al * h.z; acc.w += al * h.w;
    }
    s += __shfl_xor_sync(0xffffffffu, s, 16);
    acc.x += __shfl_xor_sync(0xffffffffu, acc.x, 16);
    acc.y += __shfl_xor_sync(0xffffffffu, acc.y, 16);
    acc.z += __shfl_xor_sync(0xffffffffu, acc.z, 16);
    acc.w += __shfl_xor_sync(0xffffffffu, acc.w, 16);
    float inv = 1.f / (s + 1e-16f);
    if (lane < 16)
        *(float4*)&g_agg[(size_t)w * D + 4 * sl] =
            make_float4(acc.x * inv, acc.y * inv, acc.z * inv, acc.w * inv);
}

// ---------------- K_mm2: out = feat_dst@W1 + agg@out_w[64:] + b (K=192) -----
// same scheme; A phase 1 from feat_dst (K=128), phase 2 from g_agg (K=64)
#define KK2 (INC + D)
#define SMW2 (KK2 * 32 * 8)          // 48 KB
__global__ void __launch_bounds__(256)
k_mm2(const float* __restrict__ feat_dst, const float* __restrict__ out_w,
      const float* __restrict__ out_b, float* __restrict__ out, int n_rows) {
    extern __shared__ unsigned long long Ws2[];   // [k][32 pairs], k<192
    int t = threadIdx.x;
    const float4* w14 = (const float4*)g_W1;
    for (int i = t; i < INC * 16; i += 256) {
        float4 v = w14[i];
        int k = i >> 4, c4 = i & 15;
        Ws2[k * 32 + c4 * 2]     = pk2(v.x, v.y);
        Ws2[k * 32 + c4 * 2 + 1] = pk2(v.z, v.w);
    }
    const float4* ow4 = (const float4*)(out_w + (size_t)D * D);
    for (int i = t; i < D * 16; i += 256) {
        float4 v = ow4[i];
        int k = INC + (i >> 4), c4 = i & 15;
        Ws2[k * 32 + c4 * 2]     = pk2(v.x, v.y);
        Ws2[k * 32 + c4 * 2 + 1] = pk2(v.z, v.w);
    }
    __syncthreads();
    int row0 = blockIdx.x * 128;
    int tx = t & 7, ty = t >> 3;
    int r0 = row0 + ty * 4;
    const float4* rp[4];
    const float4* ap[4];
    #pragma unroll
    for (int i = 0; i < 4; i++) {
        int r = r0 + i; if (r > n_rows - 1) r = n_rows - 1;
        rp[i] = (const float4*)(feat_dst + (size_t)r * INC);
        ap[i] = (const float4*)(g_agg + (size_t)r * D);
    }
    int cA = tx * 4, cB = 32 + tx * 4;
    float4 obA = *(const float4*)&out_b[cA];
    float4 obB = *(const float4*)&out_b[cB];
    unsigned long long acc[4][4];
    #pragma unroll
    for (int i = 0; i < 4; i++) {
        acc[i][0] = pk2(obA.x, obA.y); acc[i][1] = pk2(obA.z, obA.w);
        acc[i][2] = pk2(obB.x, obB.y); acc[i][3] = pk2(obB.z, obB.w);
    }
    for (int kk = 0; kk < 48; kk++) {
        float4 av[4];
        #pragma unroll
        for (int i = 0; i < 4; i++)
            av[i] = (kk < 32) ? __ldg(&rp[i][kk]) : __ldg(&ap[i][kk - 32]);
        #pragma unroll
        for (int j = 0; j < 4; j++) {
            int k = kk * 4 + j;
            ulonglong2 bA = *(const ulonglong2*)&Ws2[k * 32 + tx * 2];
            ulonglong2 bB = *(const ulonglong2*)&Ws2[k * 32 + 16 + tx * 2];
            #pragma unroll
            for (int i = 0; i < 4; i++) {
                float a = (j == 0) ? av[i].x : (j == 1) ? av[i].y
                        : (j == 2) ? av[i].z : av[i].w;
                unsigned long long aa = pk2(a, a);
                fma2(acc[i][0], aa, bA.x);
                fma2(acc[i][1], aa, bA.y);
                fma2(acc[i][2], aa, bB.x);
                fma2(acc[i][3], aa, bB.y);
            }
        }
    }
    #pragma unroll
    for (int i = 0; i < 4; i++) {
        int r = r0 + i;
        if (r < n_rows) {
            float2 p0 = up2(acc[i][0]), p1 = up2(acc[i][1]);
            float2 p2 = up2(acc[i][2]), p3 = up2(acc[i][3]);
            *(float4*)&out[(size_t)r * D + cA] = make_float4(p0.x, p0.y, p1.x, p1.y);
            *(float4*)&out[(size_t)r * D + cB] = make_float4(p2.x, p2.y, p3.x, p3.y);
        }
    }
}

// ---------------------------------------------------------------------------
extern "C" void kernel_launch(void* const* d_in, const int* in_sizes, int n_in,
                              void* d_out, int out_size) {
    const float* feat_src    = (const float*)d_in[0];
    const float* feat_dst    = (const float*)d_in[1];
    const float* edge_weight = (const float*)d_in[2];
    const int*   src_idx     = (const int*)d_in[3];
    const int*   dst_idx     = (const int*)d_in[4];
    const float* weight_n    = (const float*)d_in[5];
    const float* weight_e    = (const float*)d_in[6];
    const float* query       = (const float*)d_in[7];
    const float* key_w       = (const float*)d_in[8];
    const float* att_w       = (const float*)d_in[9];
    const float* att_b       = (const float*)d_in[10];
    const float* out_w       = (const float*)d_in[11];
    const float* out_b       = (const float*)d_in[12];
    float* out = (float*)d_out;

    int n_nodes = in_sizes[0] / INC;
    int n_edges = in_sizes[3];
    int nb = (n_nodes + 127) / 128;

    cudaFuncSetAttribute(k_mm1, cudaFuncAttributeMaxDynamicSharedMemorySize, SMW1);
    cudaFuncSetAttribute(k_mm2, cudaFuncAttributeMaxDynamicSharedMemorySize, SMW2);

    int prep_blocks = 33 + (n_edges + 1 + 255) / 256;
    k_prep<<<prep_blocks, 256>>>(weight_n, weight_e, query, key_w, att_w,
                                 out_w, dst_idx, n_nodes, n_edges);
    k_mm1<<<nb, 256, SMW1>>>(feat_src, weight_n, n_nodes);
    k_agg<<<(n_nodes * 32 + 255) / 256, 256>>>(src_idx, edge_weight, feat_dst,
                                               att_b, n_nodes);
    k_mm2<<<nb, 256, SMW2>>>(feat_dst, out_w, out_b, out, n_nodes);
}

// round 10
// speedup vs baseline: 1.8606x; 1.0663x over previous
#include <cuda_runtime.h>
#include <math.h>
#include <cstdint>

#define NN 50000
#define NE 800000
#define INC 128
#define D 64

// ---------------- scratch (static device globals; no allocation) ------------
__device__ float g_vq[INC];          // weight_n @ (query @ att_w[:d])
__device__ float g_tk[D];            // key_w @ att_w[d:2d]
__device__ float g_ce;               // weight_e[0,:] . att_w[2d:]
__device__ float g_W1[INC * D];      // weight_n @ out_w[:d]
__device__ float g_hsrc[(size_t)NN * D];
__device__ float g_ka[NN];
__device__ float g_agg[(size_t)NN * D];
__device__ int   g_start[NN + 1];

// ---------------- packed f32x2 helpers (Blackwell FFMA2) --------------------
__device__ __forceinline__ unsigned long long pk2(float lo, float hi) {
    unsigned long long r;
    asm("mov.b64 %0, {%1, %2};" : "=l"(r) : "f"(lo), "f"(hi));
    return r;
}
__device__ __forceinline__ void fma2(unsigned long long& d,
                                     unsigned long long a, unsigned long long b) {
    asm("fma.rn.f32x2 %0, %1, %2, %0;" : "+l"(d) : "l"(a), "l"(b));
}
__device__ __forceinline__ float2 up2(unsigned long long v) {
    float lo, hi;
    asm("mov.b64 {%0, %1}, %2;" : "=f"(lo), "=f"(hi) : "l"(v));
    return make_float2(lo, hi);
}

// ---------------- K_prep: fold small mats + segment bounds (one launch) -----
__global__ void k_prep(const float* __restrict__ wn,
                       const float* __restrict__ we,
                       const float* __restrict__ query,
                       const float* __restrict__ key_w,
                       const float* __restrict__ att_w,
                       const float* __restrict__ out_w,
                       const int* __restrict__ dst,
                       int n_nodes, int n_edges) {
    int t = threadIdx.x;
    if (blockIdx.x < 32) {
        int idx = blockIdx.x * 256 + t;      // 8192 outputs of W1
        int k = idx >> 6, c = idx & 63;
        float s = 0.f;
        #pragma unroll 8
        for (int j = 0; j < D; j++) s += wn[k * D + j] * out_w[j * D + c];
        g_W1[idx] = s;
        return;
    }
    if (blockIdx.x > 32) {
        int e = (blockIdx.x - 33) * 256 + t;
        if (e > n_edges) return;
        int d1 = (e < n_edges) ? dst[e] : n_nodes;
        int d0 = (e > 0) ? dst[e - 1] : -1;
        for (int n = d0 + 1; n <= d1; n++) g_start[n] = e;
        return;
    }
    __shared__ float s_aw[3 * D];
    __shared__ float s_tq[D];
    for (int i = t; i < 3 * D; i += 256) s_aw[i] = att_w[i];
    __syncthreads();
    if (t < D) {
        float sq = 0.f, sk = 0.f;
        #pragma unroll 8
        for (int j = 0; j < D; j++) {
            sq += query[t * D + j] * s_aw[j];
            sk += key_w[t * D + j] * s_aw[D + j];
        }
        s_tq[t] = sq;
        g_tk[t] = sk;
    }
    if (t == 64) {
        float c = 0.f;
        for (int j = 0; j < D; j++) c += we[j] * s_aw[2 * D + j];
        g_ce = c;
    }
    __syncthreads();
    if (t < INC) {
        float vq = 0.f;
        #pragma unroll 8
        for (int i = 0; i < D; i++) vq += wn[t * D + i] * s_tq[i];
        g_vq[t] = vq;
    }
}

// ---------------- K_mm1: h_src = feat_src @ W_n  (+ ka epilogue) ------------
// 128 rows/block, 256 threads, 4x8 micro-tile.
// A read straight from gmem (8-lane broadcast), B pre-packed f32x2 in smem.
#define SMW1 (INC * 32 * 8)          // 32 KB of packed pairs
__global__ void __launch_bounds__(256, 3)
k_mm1(const float* __restrict__ feat, const float* __restrict__ wn, int n_rows) {
    extern __shared__ unsigned long long Ws2[];   // [k][32 pairs]
    int t = threadIdx.x;
    const float4* wn4 = (const float4*)wn;
    for (int i = t; i < INC * 16; i += 256) {
        float4 v = wn4[i];
        int k = i >> 4, c4 = i & 15;
        Ws2[k * 32 + c4 * 2]     = pk2(v.x, v.y);
        Ws2[k * 32 + c4 * 2 + 1] = pk2(v.z, v.w);
    }
    __syncthreads();
    int row0 = blockIdx.x * 128;
    int tx = t & 7, ty = t >> 3;
    int r0 = row0 + ty * 4;
    const float4* rp[4];
    #pragma unroll
    for (int i = 0; i < 4; i++) {
        int r = r0 + i; if (r > n_rows - 1) r = n_rows - 1;
        rp[i] = (const float4*)(feat + (size_t)r * INC);
    }
    int cA = tx * 4, cB = 32 + tx * 4;
    unsigned long long acc[4][4] = {};
    for (int kk = 0; kk < 32; kk++) {
        float4 av[4];
        #pragma unroll
        for (int i = 0; i < 4; i++) av[i] = __ldg(&rp[i][kk]);
        #pragma unroll
        for (int j = 0; j < 4; j++) {
            int k = kk * 4 + j;
            ulonglong2 bA = *(const ulonglong2*)&Ws2[k * 32 + tx * 2];
            ulonglong2 bB = *(const ulonglong2*)&Ws2[k * 32 + 16 + tx * 2];
            #pragma unroll
            for (int i = 0; i < 4; i++) {
                float a = (j == 0) ? av[i].x : (j == 1) ? av[i].y
                        : (j == 2) ? av[i].z : av[i].w;
                unsigned long long aa = pk2(a, a);
                fma2(acc[i][0], aa, bA.x);
                fma2(acc[i][1], aa, bA.y);
                fma2(acc[i][2], aa, bB.x);
                fma2(acc[i][3], aa, bB.y);
            }
        }
    }
    float tkA[4], tkB[4];
    #pragma unroll
    for (int j = 0; j < 4; j++) { tkA[j] = g_tk[cA + j]; tkB[j] = g_tk[cB + j]; }
    #pragma unroll
    for (int i = 0; i < 4; i++) {
        int r = r0 + i;
        float2 p0 = up2(acc[i][0]), p1 = up2(acc[i][1]);
        float2 p2 = up2(acc[i][2]), p3 = up2(acc[i][3]);
        if (r < n_rows) {
            *(float4*)&g_hsrc[(size_t)r * D + cA] = make_float4(p0.x, p0.y, p1.x, p1.y);
            *(float4*)&g_hsrc[(size_t)r * D + cB] = make_float4(p2.x, p2.y, p3.x, p3.y);
        }
        float ka = p0.x * tkA[0] + p0.y * tkA[1] + p1.x * tkA[2] + p1.y * tkA[3]
                 + p2.x * tkB[0] + p2.y * tkB[1] + p3.x * tkB[2] + p3.y * tkB[3];
        ka += __shfl_xor_sync(0xffffffffu, ka, 1);
        ka += __shfl_xor_sync(0xffffffffu, ka, 2);
        ka += __shfl_xor_sync(0xffffffffu, ka, 4);
        if (tx == 0 && r < n_rows) g_ka[r] = ka;
    }
}

// ---------------- K_agg: qa + softmax + message sum, ONE pass (warp/node) ---
__global__ void k_agg(const int* __restrict__ src_idx,
                      const float* __restrict__ ew,
                      const float* __restrict__ feat_dst,
                      const float* __restrict__ att_b, int n_nodes) {
    int w = (blockIdx.x * blockDim.x + threadIdx.x) >> 5;
    int lane = threadIdx.x & 31;
    if (w >= n_nodes) return;
    int sl = lane & 15, half = lane >> 4;
    int e0 = g_start[w], e1 = g_start[w + 1];
    if (e0 == e1) {
        if (lane < 16) *(float4*)&g_agg[(size_t)w * D + 4 * sl] =
            make_float4(0.f, 0.f, 0.f, 0.f);
        return;
    }
    float4 f = ((const float4*)(feat_dst + (size_t)w * INC))[lane];
    float4 v = ((const float4*)g_vq)[lane];
    float qa = f.x * v.x + f.y * v.y + f.z * v.z + f.w * v.w;
    #pragma unroll
    for (int o = 16; o > 0; o >>= 1) qa += __shfl_xor_sync(0xffffffffu, qa, o);
    float qn = qa + att_b[0];
    float ce = g_ce;
    float s = 0.f;
    float4 acc = make_float4(0.f, 0.f, 0.f, 0.f);
    for (int e = e0 + half; e < e1; e += 2) {
        int si = src_idx[e];
        float x = qn + g_ka[si] + ew[e] * ce;
        x = (x >= 0.f) ? x : 0.2f * x;
        float al = __expf(x);
        s += al;
        float4 h = *(const float4*)&g_hsrc[(size_t)si * D + 4 * sl];
        acc.x += al * h.x; acc.y += al * h.y; acc.z += al * h.z; acc.w += al * h.w;
    }
    s += __shfl_xor_sync(0xffffffffu, s, 16);
    acc.x += __shfl_xor_sync(0xffffffffu, acc.x, 16);
    acc.y += __shfl_xor_sync(0xffffffffu, acc.y, 16);
    acc.z += __shfl_xor_sync(0xffffffffu, acc.z, 16);
    acc.w += __shfl_xor_sync(0xffffffffu, acc.w, 16);
    float inv = 1.f / (s + 1e-16f);
    if (lane < 16)
        *(float4*)&g_agg[(size_t)w * D + 4 * sl] =
            make_float4(acc.x * inv, acc.y * inv, acc.z * inv, acc.w * inv);
}

// ---------------- K_mm2: out = feat_dst@W1 + agg@out_w[64:] + b (K=192) -----
// two sequential K phases (no per-iter select); 4x8 micro-tile
#define KK2 (INC + D)
#define SMW2 (KK2 * 32 * 8)          // 48 KB
__global__ void __launch_bounds__(256, 3)
k_mm2(const float* __restrict__ feat_dst, const float* __restrict__ out_w,
      const float* __restrict__ out_b, float* __restrict__ out, int n_rows) {
    extern __shared__ unsigned long long Ws2[];   // [k][32 pairs], k<192
    int t = threadIdx.x;
    const float4* w14 = (const float4*)g_W1;
    for (int i = t; i < INC * 16; i += 256) {
        float4 v = w14[i];
        int k = i >> 4, c4 = i & 15;
        Ws2[k * 32 + c4 * 2]     = pk2(v.x, v.y);
        Ws2[k * 32 + c4 * 2 + 1] = pk2(v.z, v.w);
    }
    const float4* ow4 = (const float4*)(out_w + (size_t)D * D);
    for (int i = t; i < D * 16; i += 256) {
        float4 v = ow4[i];
        int k = INC + (i >> 4), c4 = i & 15;
        Ws2[k * 32 + c4 * 2]     = pk2(v.x, v.y);
        Ws2[k * 32 + c4 * 2 + 1] = pk2(v.z, v.w);
    }
    __syncthreads();
    int row0 = blockIdx.x * 128;
    int tx = t & 7, ty = t >> 3;
    int r0 = row0 + ty * 4;
    int rc[4];
    #pragma unroll
    for (int i = 0; i < 4; i++) {
        int r = r0 + i; if (r > n_rows - 1) r = n_rows - 1;
        rc[i] = r;
    }
    int cA = tx * 4, cB = 32 + tx * 4;
    float4 obA = *(const float4*)&out_b[cA];
    float4 obB = *(const float4*)&out_b[cB];
    unsigned long long acc[4][4];
    #pragma unroll
    for (int i = 0; i < 4; i++) {
        acc[i][0] = pk2(obA.x, obA.y); acc[i][1] = pk2(obA.z, obA.w);
        acc[i][2] = pk2(obB.x, obB.y); acc[i][3] = pk2(obB.z, obB.w);
    }
    // phase 1: feat_dst, K = 0..127
    {
        const float4* rp[4];
        #pragma unroll
        for (int i = 0; i < 4; i++)
            rp[i] = (const float4*)(feat_dst + (size_t)rc[i] * INC);
        for (int kk = 0; kk < 32; kk++) {
            float4 av[4];
            #pragma unroll
            for (int i = 0; i < 4; i++) av[i] = __ldg(&rp[i][kk]);
            #pragma unroll
            for (int j = 0; j < 4; j++) {
                int k = kk * 4 + j;
                ulonglong2 bA = *(const ulonglong2*)&Ws2[k * 32 + tx * 2];
                ulonglong2 bB = *(const ulonglong2*)&Ws2[k * 32 + 16 + tx * 2];
                #pragma unroll
                for (int i = 0; i < 4; i++) {
                    float a = (j == 0) ? av[i].x : (j == 1) ? av[i].y
                            : (j == 2) ? av[i].z : av[i].w;
                    unsigned long long aa = pk2(a, a);
                    fma2(acc[i][0], aa, bA.x);
                    fma2(acc[i][1], aa, bA.y);
                    fma2(acc[i][2], aa, bB.x);
                    fma2(acc[i][3], aa, bB.y);
                }
            }
        }
    }
    // phase 2: agg, K = 128..191
    {
        const float4* ap[4];
        #pragma unroll
        for (int i = 0; i < 4; i++)
            ap[i] = (const float4*)(g_agg + (size_t)rc[i] * D);
        for (int kk = 0; kk < 16; kk++) {
            float4 av[4];
            #pragma unroll
            for (int i = 0; i < 4; i++) av[i] = __ldg(&ap[i][kk]);
            #pragma unroll
            for (int j = 0; j < 4; j++) {
                int k = INC + kk * 4 + j;
                ulonglong2 bA = *(const ulonglong2*)&Ws2[k * 32 + tx * 2];
                ulonglong2 bB = *(const ulonglong2*)&Ws2[k * 32 + 16 + tx * 2];
                #pragma unroll
                for (int i = 0; i < 4; i++) {
                    float a = (j == 0) ? av[i].x : (j == 1) ? av[i].y
                            : (j == 2) ? av[i].z : av[i].w;
                    unsigned long long aa = pk2(a, a);
                    fma2(acc[i][0], aa, bA.x);
                    fma2(acc[i][1], aa, bA.y);
                    fma2(acc[i][2], aa, bB.x);
                    fma2(acc[i][3], aa, bB.y);
                }
            }
        }
    }
    #pragma unroll
    for (int i = 0; i < 4; i++) {
        int r = r0 + i;
        if (r < n_rows) {
            float2 p0 = up2(acc[i][0]), p1 = up2(acc[i][1]);
            float2 p2 = up2(acc[i][2]), p3 = up2(acc[i][3]);
            *(float4*)&out[(size_t)r * D + cA] = make_float4(p0.x, p0.y, p1.x, p1.y);
            *(float4*)&out[(size_t)r * D + cB] = make_float4(p2.x, p2.y, p3.x, p3.y);
        }
    }
}

// ---------------------------------------------------------------------------
extern "C" void kernel_launch(void* const* d_in, const int* in_sizes, int n_in,
                              void* d_out, int out_size) {
    const float* feat_src    = (const float*)d_in[0];
    const float* feat_dst    = (const float*)d_in[1];
    const float* edge_weight = (const float*)d_in[2];
    const int*   src_idx     = (const int*)d_in[3];
    const int*   dst_idx     = (const int*)d_in[4];
    const float* weight_n    = (const float*)d_in[5];
    const float* weight_e    = (const float*)d_in[6];
    const float* query       = (const float*)d_in[7];
    const float* key_w       = (const float*)d_in[8];
    const float* att_w       = (const float*)d_in[9];
    const float* att_b       = (const float*)d_in[10];
    const float* out_w       = (const float*)d_in[11];
    const float* out_b       = (const float*)d_in[12];
    float* out = (float*)d_out;

    int n_nodes = in_sizes[0] / INC;
    int n_edges = in_sizes[3];
    int nb = (n_nodes + 127) / 128;

    cudaFuncSetAttribute(k_mm1, cudaFuncAttributeMaxDynamicSharedMemorySize, SMW1);
    cudaFuncSetAttribute(k_mm2, cudaFuncAttributeMaxDynamicSharedMemorySize, SMW2);

    int prep_blocks = 33 + (n_edges + 1 + 255) / 256;
    k_prep<<<prep_blocks, 256>>>(weight_n, weight_e, query, key_w, att_w,
                                 out_w, dst_idx, n_nodes, n_edges);
    k_mm1<<<nb, 256, SMW1>>>(feat_src, weight_n, n_nodes);
    k_agg<<<(n_nodes * 32 + 255) / 256, 256>>>(src_idx, edge_weight, feat_dst,
                                               att_b, n_nodes);
    k_mm2<<<nb, 256, SMW2>>>(feat_dst, out_w, out_b, out, n_nodes);
}